// round 16
// baseline (speedup 1.0000x reference)
#include <cuda_runtime.h>
#include <cooperative_groups.h>
#include <math.h>
#include <float.h>

namespace cg = cooperative_groups;

// Problem constants
#define NB 8
#define NN 2048
#define NC 128
#define NCH 128     // chunks per batch
#define CSZ 16      // chunk size (NCH*CSZ == NN)
#define NP (NN+1)   // prefix length 2049

// ---------------- scratch (device globals; no allocation) ----------------
__device__ float g_h[NB*NN*NC];        // h = text @ W
__device__ float g_s1[NB*NN];
__device__ float g_s2[NB*NN];
__device__ float g_s2s[NB*NN];         // sorted s2 (ascending, via rank scatter)
__device__ int   g_perm[NB*NN];        // permutation of sort
__device__ float g_wA[NB*NN];          // e^{s2s - m2}
__device__ float g_wB[NB*NN];          // e^{0.2(s2s - m2)}
__device__ float g_m2[NB];
__device__ float2 g_chT[NB*NC*NCH];    // TRANSPOSED chunk aggregates [b][f][c]
__device__ float2 g_ch[NB*(NCH+1)*NC]; // exclusive bases; [NCH]=totals
__device__ float2 g_sagg[NB*NCH];      // scalar chunk aggregates
__device__ float2 g_sch[NB*(NCH+1)];   // scalar exclusive bases; [NCH]=totals
__device__ float2 g_srel[NB*NP];       // intra-chunk relative scalar prefixes
__device__ float2 g_P[NB*NP*NC];       // intra-chunk RELATIVE vector prefixes

// ---------------- f32x2 packed-FMA helpers (sm_103a FFMA2) ----------------
__device__ __forceinline__ unsigned long long pack2(float x, float y) {
    unsigned long long r;
    asm("mov.b64 %0, {%1, %2};" : "=l"(r) : "f"(x), "f"(y));
    return r;
}
__device__ __forceinline__ void unpack2(unsigned long long v, float& x, float& y) {
    asm("mov.b64 {%0, %1}, %2;" : "=f"(x), "=f"(y) : "l"(v));
}
__device__ __forceinline__ void ffma2(unsigned long long& d, unsigned long long a, unsigned long long b) {
    asm("fma.rn.f32x2 %0, %1, %2, %0;" : "+l"(d) : "l"(a), "l"(b));
}

// ---------------- Kernel 1: GEMM h = text@W (f32x2), fused s1/s2 ----------------
__global__ void __launch_bounds__(256) gemm_kernel(const float* __restrict__ A,
                                                   const float* __restrict__ W,
                                                   const float* __restrict__ avec)
{
    __shared__ float As[16][64];
    __shared__ float Bs[16][128];
    const int b  = blockIdx.y;
    const int m0 = blockIdx.x * 64;
    const int tid = threadIdx.x;
    const int tx = tid & 31;
    const int ty = tid >> 5;
    const float* Ab = A + (size_t)(b*NN + m0) * NC;

    unsigned long long acc2[4][4];
#pragma unroll
    for (int p = 0; p < 4; p++)
#pragma unroll
        for (int j = 0; j < 4; j++) acc2[p][j] = 0ull;

    const int ar = tid >> 2;
    const int ac = (tid & 3) * 4;

    for (int k0 = 0; k0 < 128; k0 += 16) {
        float4 av = *(const float4*)(Ab + (size_t)ar*NC + k0 + ac);
        As[ac+0][ar] = av.x; As[ac+1][ar] = av.y;
        As[ac+2][ar] = av.z; As[ac+3][ar] = av.w;
#pragma unroll
        for (int it = 0; it < 2; it++) {
            int idx = tid + 256*it;
            int brr = idx >> 5, bcc = (idx & 31) * 4;
            *(float4*)&Bs[brr][bcc] = *(const float4*)(W + (size_t)(k0+brr)*NC + bcc);
        }
        __syncthreads();
#pragma unroll
        for (int kk = 0; kk < 16; kk++) {
            float4 a03 = *(const float4*)&As[kk][ty*8];
            float4 a47 = *(const float4*)&As[kk][ty*8 + 4];
            float4 bv  = *(const float4*)&Bs[kk][tx*4];
            unsigned long long ap[4];
            ap[0] = pack2(a03.x, a03.y); ap[1] = pack2(a03.z, a03.w);
            ap[2] = pack2(a47.x, a47.y); ap[3] = pack2(a47.z, a47.w);
            unsigned long long bd[4];
            bd[0] = pack2(bv.x, bv.x); bd[1] = pack2(bv.y, bv.y);
            bd[2] = pack2(bv.z, bv.z); bd[3] = pack2(bv.w, bv.w);
#pragma unroll
            for (int p = 0; p < 4; p++)
#pragma unroll
                for (int j = 0; j < 4; j++) ffma2(acc2[p][j], ap[p], bd[j]);
        }
        __syncthreads();
    }

    float acc[8][4];
#pragma unroll
    for (int p = 0; p < 4; p++)
#pragma unroll
        for (int j = 0; j < 4; j++) unpack2(acc2[p][j], acc[2*p][j], acc[2*p+1][j]);

    float a1[4], a2[4];
#pragma unroll
    for (int j = 0; j < 4; j++) { a1[j] = avec[tx*4+j]; a2[j] = avec[128 + tx*4+j]; }

#pragma unroll
    for (int i = 0; i < 8; i++) {
        int row = m0 + ty*8 + i;
        float4 v = make_float4(acc[i][0], acc[i][1], acc[i][2], acc[i][3]);
        *(float4*)(g_h + (size_t)(b*NN + row)*NC + tx*4) = v;
        float d1 = acc[i][0]*a1[0] + acc[i][1]*a1[1] + acc[i][2]*a1[2] + acc[i][3]*a1[3];
        float d2 = acc[i][0]*a2[0] + acc[i][1]*a2[1] + acc[i][2]*a2[2] + acc[i][3]*a2[3];
#pragma unroll
        for (int off = 16; off > 0; off >>= 1) {
            d1 += __shfl_down_sync(0xffffffffu, d1, off);
            d2 += __shfl_down_sync(0xffffffffu, d2, off);
        }
        if (tx == 0) { g_s1[b*NN + row] = d1; g_s2[b*NN + row] = d2; }
    }
}

// ---------------- Kernel 2: rank-scatter "sort" ----------------
__global__ void __launch_bounds__(128) rank_kernel()
{
    __shared__ float keys[NN];
    __shared__ float red[4];
    const int b = blockIdx.y, tid = threadIdx.x;
    const int j = blockIdx.x * 128 + tid;

    for (int i = tid; i < NN; i += 128) keys[i] = g_s2[b*NN + i];
    __syncthreads();

    float mx = -FLT_MAX;
    for (int i = tid; i < NN; i += 128) mx = fmaxf(mx, keys[i]);
#pragma unroll
    for (int off = 16; off > 0; off >>= 1)
        mx = fmaxf(mx, __shfl_xor_sync(0xffffffffu, mx, off));
    if ((tid & 31) == 0) red[tid >> 5] = mx;
    __syncthreads();
    const float m2v = fmaxf(fmaxf(red[0], red[1]), fmaxf(red[2], red[3]));
    if (blockIdx.x == 0 && tid == 0) g_m2[b] = m2v;

    const float k = keys[j];
    const float4* k4 = (const float4*)keys;
    int rank = 0;
#pragma unroll 4
    for (int q = 0; q < NN/4; q++) {
        float4 v = k4[q];
        int jj = q*4;
        rank += (v.x < k) || (v.x == k && jj+0 < j);
        rank += (v.y < k) || (v.y == k && jj+1 < j);
        rank += (v.z < k) || (v.z == k && jj+2 < j);
        rank += (v.w < k) || (v.w == k && jj+3 < j);
    }

    const float s = k - m2v;
    const int o = b*NN + rank;
    g_s2s[o]  = k;
    g_perm[o] = j;
    g_wA[o]   = expf(s);
    g_wB[o]   = expf(0.2f * s);
}

// ---------------- Kernel 3: cooperative tail = relexpand + scan + query ----------------
// grid 1024 x 128, cooperative. __launch_bounds__(128,8): 8 blocks/SM * 148 = 1184 >= 1024.
__global__ void __launch_bounds__(128, 8) tail_kernel(float* __restrict__ out)
{
    cg::grid_group grid = cg::this_grid();
    __shared__ union SM {
        struct { float wa[CSZ]; float wb[CSZ]; int js[CSZ]; } rel;
        struct { float s2sh[NN]; int ks[16]; float s1s[16]; } qry;
    } sm;

    const int beta = blockIdx.x;

    // ======== Stage 1: relexpand ========
    {
        const int b = beta >> 7, c = beta & 127, f = threadIdx.x;
        const int base = b*NN + c*CSZ;
        if (f < CSZ) {
            sm.rel.wa[f] = g_wA[base + f];
            sm.rel.wb[f] = g_wB[base + f];
            sm.rel.js[f] = g_perm[base + f];
        }
        __syncthreads();

        float hv[CSZ];
#pragma unroll
        for (int r = 0; r < CSZ; r++) hv[r] = g_h[(size_t)(b*NN + sm.rel.js[r])*NC + f];

        float runA = 0.f, runB = 0.f;
        size_t p = (size_t)(b*NP + c*CSZ)*NC + f;
#pragma unroll
        for (int r = 0; r < CSZ; r++) {
            g_P[p] = make_float2(runA, runB);
            runA = fmaf(sm.rel.wa[r], hv[r], runA);
            runB = fmaf(sm.rel.wb[r], hv[r], runB);
            p += NC;
        }
        g_chT[(size_t)(b*NC + f)*NCH + c] = make_float2(runA, runB);
        if (c == NCH-1) g_P[p] = make_float2(0.f, 0.f);

        if (f == 0) {
            float ra = 0.f, rb = 0.f;
#pragma unroll
            for (int r = 0; r < CSZ; r++) {
                g_srel[b*NP + c*CSZ + r] = make_float2(ra, rb);
                ra += sm.rel.wa[r]; rb += sm.rel.wb[r];
            }
            g_sagg[b*NCH + c] = make_float2(ra, rb);
            if (c == NCH-1) g_srel[b*NP + NN] = make_float2(0.f, 0.f);
        }
        __syncthreads();
    }

    grid.sync();

    // ======== Stage 2: scan (vector + scalar) ========
    if (beta < 256) {
        const int b = beta >> 5, g = beta & 31;
        const int w = threadIdx.x >> 5, lane = threadIdx.x & 31;
        const int f = g*4 + w;       // 32 block-groups * 4 warps = 128 features
        const size_t tb = (size_t)(b*NC + f)*NCH;

        float2 v[4];
#pragma unroll
        for (int u = 0; u < 4; u++) v[u] = g_chT[tb + lane*4 + u];

        float ownA = (v[0].x + v[1].x) + (v[2].x + v[3].x);
        float ownB = (v[0].y + v[1].y) + (v[2].y + v[3].y);
        float sA = ownA, sB = ownB;
#pragma unroll
        for (int off = 1; off < 32; off <<= 1) {
            float nA = __shfl_up_sync(0xffffffffu, sA, off);
            float nB = __shfl_up_sync(0xffffffffu, sB, off);
            if (lane >= off) { sA += nA; sB += nB; }
        }
        float eA = sA - ownA, eB = sB - ownB;
#pragma unroll
        for (int u = 0; u < 4; u++) {
            g_ch[(size_t)(b*(NCH+1) + lane*4 + u)*NC + f] = make_float2(eA, eB);
            eA += v[u].x; eB += v[u].y;
        }
        if (lane == 31) g_ch[(size_t)(b*(NCH+1)+NCH)*NC + f] = make_float2(sA, sB);

        if (g == 0 && w == 0) {
            float2 s[4];
#pragma unroll
            for (int u = 0; u < 4; u++) s[u] = g_sagg[b*NCH + lane*4 + u];
            float oA = (s[0].x + s[1].x) + (s[2].x + s[3].x);
            float oB = (s[0].y + s[1].y) + (s[2].y + s[3].y);
            float tA = oA, tB = oB;
#pragma unroll
            for (int off = 1; off < 32; off <<= 1) {
                float nA = __shfl_up_sync(0xffffffffu, tA, off);
                float nB = __shfl_up_sync(0xffffffffu, tB, off);
                if (lane >= off) { tA += nA; tB += nB; }
            }
            float xA = tA - oA, xB = tB - oB;
#pragma unroll
            for (int u = 0; u < 4; u++) {
                g_sch[b*(NCH+1) + lane*4 + u] = make_float2(xA, xB);
                xA += s[u].x; xB += s[u].y;
            }
            if (lane == 31) g_sch[b*(NCH+1)+NCH] = make_float2(tA, tB);
        }
    }

    grid.sync();

    // ======== Stage 3: query ========
    {
        const int b = beta >> 7, f = threadIdx.x;
        const int qbase = (beta & 127) * 16;
        for (int i = f; i < NN; i += 128) sm.qry.s2sh[i] = g_s2s[b*NN + i];
        __syncthreads();

        if (f < 16) {
            const int i = qbase + f;
            const float s1v = g_s1[b*NN + i];
            sm.qry.s1s[f] = s1v;
            const float t = -s1v;
            int k = 0;
#pragma unroll
            for (int st = 2048; st > 0; st >>= 1) {
                int nk = k + st;
                if (nk <= NN && sm.qry.s2sh[nk-1] <= t) k = nk;
            }
            sm.qry.ks[f] = k;
        }
        __syncthreads();

        const float m2v = g_m2[b];
        const float taf = g_ch[(size_t)(b*(NCH+1)+NCH)*NC + f].x;
        const float tas = g_sch[b*(NCH+1)+NCH].x;

#pragma unroll 4
        for (int qi = 0; qi < 16; qi++) {
            const int i = qbase + qi;
            const int k = sm.qry.ks[qi];
            const float s1v = sm.qry.s1s[qi];
            const int c = k >> 4;
            const float2 bse = g_ch[(size_t)(b*(NCH+1)+c)*NC + f];
            const float2 rel = g_P[(size_t)(b*NP + k)*NC + f];
            const float2 sb2 = g_sch[b*(NCH+1)+c];
            const float2 sr2 = g_srel[b*NP + k];
            const float PAk = bse.x + rel.x;
            const float PBk = bse.y + rel.y;
            const float sap = sb2.x + sr2.x;
            const float sbp = sb2.y + sr2.y;
            const float SA = taf - PAk, SB = PBk;
            const float sa = tas - sap, sb = sbp;
            const float u = s1v + m2v;
            float hp;
            if (u > 0.f) {
                float inv = expf(-0.8f * u);
                hp = (SA + inv*SB) / (sa + inv*sb);
            } else {
                float fc = expf(0.8f * u);
                hp = (fc*SA + SB) / (fc*sa + sb);
            }
            const float hvi = g_h[(size_t)(b*NN + i)*NC + f];
            const float x = hp + 0.2f * hvi;
            out[(size_t)(b*NN + i)*NC + f] = (x > 0.f) ? x : expm1f(x);
        }
    }
}

// ---------------- launch ----------------
extern "C" void kernel_launch(void* const* d_in, const int* in_sizes, int n_in,
                              void* d_out, int out_size)
{
    int iText = 0, iW = 2, iA = 3;
    for (int i = 0; i < n_in; i++) {
        if (in_sizes[i] == NB*NN*NC) iText = i;
        else if (in_sizes[i] == NC*NC) iW = i;
        else if (in_sizes[i] == 2*NC) iA = i;
    }
    const float* text = (const float*)d_in[iText];
    const float* W    = (const float*)d_in[iW];
    const float* avec = (const float*)d_in[iA];
    float* out = (float*)d_out;

    gemm_kernel<<<dim3(NN/64, NB), 256>>>(text, W, avec);
    rank_kernel<<<dim3(16, NB), 128>>>();

    cudaLaunchConfig_t cfg = {};
    cfg.gridDim  = dim3(1024, 1, 1);
    cfg.blockDim = dim3(128, 1, 1);
    cfg.dynamicSmemBytes = 0;
    cudaLaunchAttribute attrs[1];
    attrs[0].id = cudaLaunchAttributeCooperative;
    attrs[0].val.cooperative = 1;
    cfg.attrs = attrs;
    cfg.numAttrs = 1;
    cudaLaunchKernelEx(&cfg, tail_kernel, out);
}

// round 17
// speedup vs baseline: 1.0887x; 1.0887x over previous
#include <cuda_runtime.h>
#include <math.h>
#include <float.h>

// Problem constants
#define NB 8
#define NN 2048
#define NC 128
#define NCH 128     // chunks per batch
#define CSZ 16      // chunk size (NCH*CSZ == NN)
#define NP (NN+1)   // prefix length 2049

// ---------------- scratch (device globals; no allocation) ----------------
__device__ float g_h[NB*NN*NC];        // h = text @ W
__device__ float g_s1[NB*NN];
__device__ float g_s2[NB*NN];
__device__ float g_s2s[NB*NN];         // sorted s2 (ascending, via rank scatter)
__device__ int   g_perm[NB*NN];        // permutation of sort
__device__ float g_wA[NB*NN];          // e^{s2s - m2}
__device__ float g_wB[NB*NN];          // e^{0.2(s2s - m2)}
__device__ float g_m2[NB];
__device__ float2 g_chT[NB*NC*NCH];    // TRANSPOSED chunk aggregates [b][f][c]
__device__ float2 g_ch[NB*(NCH+1)*NC]; // exclusive bases (written by scan); [NCH]=totals
__device__ float2 g_sagg[NB*NCH];      // scalar chunk aggregates
__device__ float2 g_sch[NB*(NCH+1)];   // scalar exclusive bases; [NCH]=totals
__device__ float2 g_srel[NB*NP];       // intra-chunk relative scalar prefixes
__device__ float2 g_P[NB*NP*NC];       // intra-chunk RELATIVE vector prefixes

// ---------------- f32x2 packed-FMA helpers (sm_103a FFMA2) ----------------
__device__ __forceinline__ unsigned long long pack2(float x, float y) {
    unsigned long long r;
    asm("mov.b64 %0, {%1, %2};" : "=l"(r) : "f"(x), "f"(y));
    return r;
}
__device__ __forceinline__ void unpack2(unsigned long long v, float& x, float& y) {
    asm("mov.b64 {%0, %1}, %2;" : "=f"(x), "=f"(y) : "l"(v));
}
__device__ __forceinline__ void ffma2(unsigned long long& d, unsigned long long a, unsigned long long b) {
    asm("fma.rn.f32x2 %0, %1, %2, %0;" : "+l"(d) : "l"(a), "l"(b));
}

// ---------------- Kernel 1: GEMM h = text@W, 128x128 tile, 8x8 microtile (f32x2) ----------------
// grid (NN/128, NB) x 256. One block per SM wave. Fused s1/s2 epilogue.
__global__ void __launch_bounds__(256) gemm_kernel(const float* __restrict__ A,
                                                   const float* __restrict__ W,
                                                   const float* __restrict__ avec)
{
    __shared__ float As[16][128];   // [k][row]
    __shared__ float Bs[16][128];   // [k][col]
    const int b  = blockIdx.y;
    const int m0 = blockIdx.x * 128;
    const int tid = threadIdx.x;
    const int tx = tid & 15;        // col group: 16 * 8 = 128
    const int ty = tid >> 4;        // row group: 16 * 8 = 128
    const float* Ab = A + (size_t)(b*NN + m0) * NC;

    unsigned long long acc2[4][8];  // row-pairs p (rows 2p,2p+1 of my 8) x 8 cols
#pragma unroll
    for (int p = 0; p < 4; p++)
#pragma unroll
        for (int j = 0; j < 8; j++) acc2[p][j] = 0ull;

    const int ar = tid >> 1;            // 0..127 (A row)
    const int ac = (tid & 1) * 8;       // 0 or 8 (k offset)
    const int brr = tid >> 4;           // 0..15 (B k-row)
    const int bcc = (tid & 15) * 8;     // col offset

    for (int k0 = 0; k0 < 128; k0 += 16) {
        float4 av0 = *(const float4*)(Ab + (size_t)ar*NC + k0 + ac);
        float4 av1 = *(const float4*)(Ab + (size_t)ar*NC + k0 + ac + 4);
        As[ac+0][ar] = av0.x; As[ac+1][ar] = av0.y; As[ac+2][ar] = av0.z; As[ac+3][ar] = av0.w;
        As[ac+4][ar] = av1.x; As[ac+5][ar] = av1.y; As[ac+6][ar] = av1.z; As[ac+7][ar] = av1.w;
        *(float4*)&Bs[brr][bcc]   = *(const float4*)(W + (size_t)(k0+brr)*NC + bcc);
        *(float4*)&Bs[brr][bcc+4] = *(const float4*)(W + (size_t)(k0+brr)*NC + bcc + 4);
        __syncthreads();
#pragma unroll
        for (int kk = 0; kk < 16; kk++) {
            float4 a03 = *(const float4*)&As[kk][ty*8];
            float4 a47 = *(const float4*)&As[kk][ty*8 + 4];
            float4 b03 = *(const float4*)&Bs[kk][tx*8];
            float4 b47 = *(const float4*)&Bs[kk][tx*8 + 4];
            unsigned long long ap[4];
            ap[0] = pack2(a03.x, a03.y); ap[1] = pack2(a03.z, a03.w);
            ap[2] = pack2(a47.x, a47.y); ap[3] = pack2(a47.z, a47.w);
            unsigned long long bd[8];
            bd[0] = pack2(b03.x, b03.x); bd[1] = pack2(b03.y, b03.y);
            bd[2] = pack2(b03.z, b03.z); bd[3] = pack2(b03.w, b03.w);
            bd[4] = pack2(b47.x, b47.x); bd[5] = pack2(b47.y, b47.y);
            bd[6] = pack2(b47.z, b47.z); bd[7] = pack2(b47.w, b47.w);
#pragma unroll
            for (int p = 0; p < 4; p++)
#pragma unroll
                for (int j = 0; j < 8; j++) ffma2(acc2[p][j], ap[p], bd[j]);
        }
        __syncthreads();
    }

    // unpack: acc[i][j], i = local row 0..7, j = local col 0..7
    float acc[8][8];
#pragma unroll
    for (int p = 0; p < 4; p++)
#pragma unroll
        for (int j = 0; j < 8; j++) unpack2(acc2[p][j], acc[2*p][j], acc[2*p+1][j]);

    float a1[8], a2[8];
#pragma unroll
    for (int j = 0; j < 8; j++) { a1[j] = avec[tx*8+j]; a2[j] = avec[128 + tx*8+j]; }

#pragma unroll
    for (int i = 0; i < 8; i++) {
        int row = m0 + ty*8 + i;
        *(float4*)(g_h + (size_t)(b*NN + row)*NC + tx*8)     = make_float4(acc[i][0], acc[i][1], acc[i][2], acc[i][3]);
        *(float4*)(g_h + (size_t)(b*NN + row)*NC + tx*8 + 4) = make_float4(acc[i][4], acc[i][5], acc[i][6], acc[i][7]);
        float d1 = 0.f, d2 = 0.f;
#pragma unroll
        for (int j = 0; j < 8; j++) { d1 += acc[i][j]*a1[j]; d2 += acc[i][j]*a2[j]; }
        // reduce across 16 lanes of same ty (tx = lane % 16)
#pragma unroll
        for (int off = 8; off > 0; off >>= 1) {
            d1 += __shfl_down_sync(0xffffffffu, d1, off, 16);
            d2 += __shfl_down_sync(0xffffffffu, d2, off, 16);
        }
        if (tx == 0) { g_s1[b*NN + row] = d1; g_s2[b*NN + row] = d2; }
    }
}

// ---------------- Kernel 2: rank-scatter "sort" (whole-chip parallel) ----------------
__global__ void __launch_bounds__(128) rank_kernel()
{
    __shared__ float keys[NN];
    __shared__ float red[4];
    const int b = blockIdx.y, tid = threadIdx.x;
    const int j = blockIdx.x * 128 + tid;

    for (int i = tid; i < NN; i += 128) keys[i] = g_s2[b*NN + i];
    __syncthreads();

    float mx = -FLT_MAX;
    for (int i = tid; i < NN; i += 128) mx = fmaxf(mx, keys[i]);
#pragma unroll
    for (int off = 16; off > 0; off >>= 1)
        mx = fmaxf(mx, __shfl_xor_sync(0xffffffffu, mx, off));
    if ((tid & 31) == 0) red[tid >> 5] = mx;
    __syncthreads();
    const float m2v = fmaxf(fmaxf(red[0], red[1]), fmaxf(red[2], red[3]));
    if (blockIdx.x == 0 && tid == 0) g_m2[b] = m2v;

    const float k = keys[j];
    const float4* k4 = (const float4*)keys;
    int rank = 0;
#pragma unroll 4
    for (int q = 0; q < NN/4; q++) {
        float4 v = k4[q];
        int jj = q*4;
        rank += (v.x < k) || (v.x == k && jj+0 < j);
        rank += (v.y < k) || (v.y == k && jj+1 < j);
        rank += (v.z < k) || (v.z == k && jj+2 < j);
        rank += (v.w < k) || (v.w == k && jj+3 < j);
    }

    const float s = k - m2v;
    const int o = b*NN + rank;
    g_s2s[o]  = k;
    g_perm[o] = j;
    g_wA[o]   = expf(s);
    g_wB[o]   = expf(0.2f * s);
}

// ---------------- Kernel 3: relative expand + transposed aggregates + scalar rels ----------------
__global__ void __launch_bounds__(128) relexpand_kernel()
{
    __shared__ float wa[CSZ], wb[CSZ];
    __shared__ int js[CSZ];
    const int b = blockIdx.y, c = blockIdx.x, f = threadIdx.x;
    const int base = b*NN + c*CSZ;
    if (f < CSZ) {
        wa[f] = g_wA[base + f];
        wb[f] = g_wB[base + f];
        js[f] = g_perm[base + f];
    }
    __syncthreads();

    float hv[CSZ];
#pragma unroll
    for (int r = 0; r < CSZ; r++) hv[r] = g_h[(size_t)(b*NN + js[r])*NC + f];

    float runA = 0.f, runB = 0.f;
    size_t p = (size_t)(b*NP + c*CSZ)*NC + f;
#pragma unroll
    for (int r = 0; r < CSZ; r++) {
        g_P[p] = make_float2(runA, runB);
        runA = fmaf(wa[r], hv[r], runA);
        runB = fmaf(wb[r], hv[r], runB);
        p += NC;
    }
    g_chT[(size_t)(b*NC + f)*NCH + c] = make_float2(runA, runB);
    if (c == NCH-1) g_P[p] = make_float2(0.f, 0.f);

    if (f == 0) {
        float ra = 0.f, rb = 0.f;
#pragma unroll
        for (int r = 0; r < CSZ; r++) {
            g_srel[b*NP + c*CSZ + r] = make_float2(ra, rb);
            ra += wa[r]; rb += wb[r];
        }
        g_sagg[b*NCH + c] = make_float2(ra, rb);
        if (c == NCH-1) g_srel[b*NP + NN] = make_float2(0.f, 0.f);
    }
}

// ---------------- Kernel 4: coalesced scan (vector + scalar) ----------------
__global__ void __launch_bounds__(256) scan_kernel()
{
    const int b = blockIdx.x;
    const int w = threadIdx.x >> 5, lane = threadIdx.x & 31;
    const int f = blockIdx.y * 8 + w;
    const size_t tb = (size_t)(b*NC + f)*NCH;

    float2 v[4];
#pragma unroll
    for (int u = 0; u < 4; u++) v[u] = g_chT[tb + lane*4 + u];

    float ownA = (v[0].x + v[1].x) + (v[2].x + v[3].x);
    float ownB = (v[0].y + v[1].y) + (v[2].y + v[3].y);
    float sA = ownA, sB = ownB;
#pragma unroll
    for (int off = 1; off < 32; off <<= 1) {
        float nA = __shfl_up_sync(0xffffffffu, sA, off);
        float nB = __shfl_up_sync(0xffffffffu, sB, off);
        if (lane >= off) { sA += nA; sB += nB; }
    }
    float eA = sA - ownA, eB = sB - ownB;
#pragma unroll
    for (int u = 0; u < 4; u++) {
        g_ch[(size_t)(b*(NCH+1) + lane*4 + u)*NC + f] = make_float2(eA, eB);
        eA += v[u].x; eB += v[u].y;
    }
    if (lane == 31) g_ch[(size_t)(b*(NCH+1)+NCH)*NC + f] = make_float2(sA, sB);

    if (blockIdx.y == 0 && w == 0) {
        float2 s[4];
#pragma unroll
        for (int u = 0; u < 4; u++) s[u] = g_sagg[b*NCH + lane*4 + u];
        float oA = (s[0].x + s[1].x) + (s[2].x + s[3].x);
        float oB = (s[0].y + s[1].y) + (s[2].y + s[3].y);
        float tA = oA, tB = oB;
#pragma unroll
        for (int off = 1; off < 32; off <<= 1) {
            float nA = __shfl_up_sync(0xffffffffu, tA, off);
            float nB = __shfl_up_sync(0xffffffffu, tB, off);
            if (lane >= off) { tA += nA; tB += nB; }
        }
        float xA = tA - oA, xB = tB - oB;
#pragma unroll
        for (int u = 0; u < 4; u++) {
            g_sch[b*(NCH+1) + lane*4 + u] = make_float2(xA, xB);
            xA += s[u].x; xB += s[u].y;
        }
        if (lane == 31) g_sch[b*(NCH+1)+NCH] = make_float2(tA, tB);
    }
}

// ---------------- Kernel 5: per-query output (base + relative prefix) ----------------
__global__ void __launch_bounds__(128) query_kernel(float* __restrict__ out)
{
    __shared__ float s2sh[NN];
    __shared__ int   ks[16];
    __shared__ float s1s[16];
    const int b = blockIdx.y, f = threadIdx.x;
    const int qbase = blockIdx.x * 16;
    for (int i = f; i < NN; i += 128) s2sh[i] = g_s2s[b*NN + i];
    __syncthreads();

    if (f < 16) {
        const int i = qbase + f;
        const float s1v = g_s1[b*NN + i];
        s1s[f] = s1v;
        const float t = -s1v;
        int k = 0;
#pragma unroll
        for (int st = 2048; st > 0; st >>= 1) {
            int nk = k + st;
            if (nk <= NN && s2sh[nk-1] <= t) k = nk;
        }
        ks[f] = k;
    }
    __syncthreads();

    const float m2v = g_m2[b];
    const float taf = g_ch[(size_t)(b*(NCH+1)+NCH)*NC + f].x;
    const float tas = g_sch[b*(NCH+1)+NCH].x;

#pragma unroll 4
    for (int qi = 0; qi < 16; qi++) {
        const int i = qbase + qi;
        const int k = ks[qi];
        const float s1v = s1s[qi];
        const int c = k >> 4;                    // k==NN -> c==NCH (totals base)
        const float2 bse = g_ch[(size_t)(b*(NCH+1)+c)*NC + f];
        const float2 rel = g_P[(size_t)(b*NP + k)*NC + f];
        const float2 sb2 = g_sch[b*(NCH+1)+c];
        const float2 sr2 = g_srel[b*NP + k];
        const float PAk = bse.x + rel.x;
        const float PBk = bse.y + rel.y;
        const float sap = sb2.x + sr2.x;
        const float sbp = sb2.y + sr2.y;
        const float SA = taf - PAk, SB = PBk;
        const float sa = tas - sap, sb = sbp;
        const float u = s1v + m2v;
        float hp;
        if (u > 0.f) {
            float inv = expf(-0.8f * u);
            hp = (SA + inv*SB) / (sa + inv*sb);
        } else {
            float fc = expf(0.8f * u);
            hp = (fc*SA + SB) / (fc*sa + sb);
        }
        const float hvi = g_h[(size_t)(b*NN + i)*NC + f];
        const float x = hp + 0.2f * hvi;
        out[(size_t)(b*NN + i)*NC + f] = (x > 0.f) ? x : expm1f(x);
    }
}

// ---------------- launch ----------------
extern "C" void kernel_launch(void* const* d_in, const int* in_sizes, int n_in,
                              void* d_out, int out_size)
{
    int iText = 0, iW = 2, iA = 3;
    for (int i = 0; i < n_in; i++) {
        if (in_sizes[i] == NB*NN*NC) iText = i;
        else if (in_sizes[i] == NC*NC) iW = i;
        else if (in_sizes[i] == 2*NC) iA = i;
    }
    const float* text = (const float*)d_in[iText];
    const float* W    = (const float*)d_in[iW];
    const float* avec = (const float*)d_in[iA];
    float* out = (float*)d_out;

    gemm_kernel<<<dim3(NN/128, NB), 256>>>(text, W, avec);
    rank_kernel<<<dim3(16, NB), 128>>>();
    relexpand_kernel<<<dim3(NCH, NB), 128>>>();
    scan_kernel<<<dim3(NB, 16), 256>>>();
    query_kernel<<<dim3(NN/16, NB), 128>>>(out);
}